// round 10
// baseline (speedup 1.0000x reference)
#include <cuda_runtime.h>
#include <cuda_fp16.h>

// Triplane sampling, GB300 (sm_103a).
// Stream A (capture): transpose s3 (fp32->fp16, 339MB)
// Stream B (forked):  hist -> scan -> scatter -> transpose s0,s1,s2 -> gather012
// join -> gather3 (block2 readback + s3 corners -> block3)
// fp16 channel-major scratch: [scale][plane][texel][72] halves (150 MB).

#define CDIM 72
#define NCHUNK_H 9           // 72 / 8 halves per uint4 chunk
#define THREADS_PER_PT 27    // 3 planes * 9 chunks
#define NBUCKET 4096

__device__ __half g_tph[75202560];     // 150.4 MB fp16 scratch
__device__ float  g_ptss[262144 * 3];  // spatially sorted points
__device__ int    g_perm[262144];      // sorted position -> original index
__device__ int    g_hist[NBUCKET];     // zero-init; scan_k restores zeros
__device__ int    g_base[NBUCKET];

__device__ __forceinline__ unsigned h2_bits(__half2 h) {
    union { __half2 h; unsigned u; } cv;
    cv.h = h;
    return cv.u;
}

// ---------------- sort: bucket key (3D Morton, 4 bits/dim) ----------------
__device__ __forceinline__ int pt_key(const float* __restrict__ pts, int n) {
    int k = 0;
    #pragma unroll
    for (int d = 0; d < 3; d++) {
        float u = fminf(fmaxf(-0.625f * pts[3 * n + d], -1.f), 1.f) * 0.5f + 0.5f;
        int q = min(15, (int)(u * 16.0f));
        #pragma unroll
        for (int b = 0; b < 4; b++)
            k |= ((q >> b) & 1) << (3 * b + d);
    }
    return k;
}

__global__ void hist_k(const float* __restrict__ pts, int N) {
    int n = blockIdx.x * blockDim.x + threadIdx.x;
    if (n < N) atomicAdd(&g_hist[pt_key(pts, n)], 1);
}

__global__ __launch_bounds__(512) void scan_k() {
    __shared__ int sh[512];
    const int t = threadIdx.x;
    int v[8];
    int s = 0;
    #pragma unroll
    for (int i = 0; i < 8; i++) { v[i] = g_hist[t * 8 + i]; s += v[i]; }
    #pragma unroll
    for (int i = 0; i < 8; i++) g_hist[t * 8 + i] = 0;  // restore for next replay
    sh[t] = s;
    __syncthreads();
    for (int off = 1; off < 512; off <<= 1) {
        int x = (t >= off) ? sh[t - off] : 0;
        __syncthreads();
        sh[t] += x;
        __syncthreads();
    }
    int excl = sh[t] - s;
    #pragma unroll
    for (int i = 0; i < 8; i++) { g_base[t * 8 + i] = excl; excl += v[i]; }
}

__global__ void scatter_k(const float* __restrict__ pts, int N) {
    int n = blockIdx.x * blockDim.x + threadIdx.x;
    if (n >= N) return;
    int pos = atomicAdd(&g_base[pt_key(pts, n)], 1);
    g_perm[pos] = n;
    g_ptss[pos * 3 + 0] = pts[n * 3 + 0];
    g_ptss[pos * 3 + 1] = pts[n * 3 + 1];
    g_ptss[pos * 3 + 2] = pts[n * 3 + 2];
}

// ---------------- transpose: [3,72,r2] fp32 -> [3, r2, 72] fp16 ----------------
__global__ __launch_bounds__(288) void transpose_k(
    const float* __restrict__ in, int off, int r2)
{
    __shared__ float tile[64 * 77];
    const int p   = blockIdx.y;
    const int t0  = blockIdx.x * 64;
    const int tid = threadIdx.x;

    const float* src = in + (size_t)p * CDIM * r2 + t0;
    #pragma unroll
    for (int i = 0; i < 4; i++) {
        int idx = i * 288 + tid;          // 0..1151
        int c = idx >> 4;                 // channel 0..71
        int v = idx & 15;                 // float4 index over 64 texels
        float4 d = __ldg((const float4*)(src + (size_t)c * r2) + v);
        float* tp = tile + (4 * v) * 77 + c;
        tp[0 * 77] = d.x;
        tp[1 * 77] = d.y;
        tp[2 * 77] = d.z;
        tp[3 * 77] = d.w;
    }
    __syncthreads();

    uint4* dst = (uint4*)(g_tph + off) + ((size_t)p * r2 + t0) * NCHUNK_H;
    #pragma unroll
    for (int i = 0; i < 2; i++) {
        int lin = i * 288 + tid;          // 0..575
        int x = lin / NCHUNK_H;
        int q = lin - x * NCHUNK_H;
        const float* tp = tile + x * 77 + 8 * q;
        uint4 o;
        o.x = h2_bits(__floats2half2_rn(tp[0], tp[1]));
        o.y = h2_bits(__floats2half2_rn(tp[2], tp[3]));
        o.z = h2_bits(__floats2half2_rn(tp[4], tp[5]));
        o.w = h2_bits(__floats2half2_rn(tp[6], tp[7]));
        dst[lin] = o;
    }
}

// ---------------- shared bilinear corner fetch ----------------
__device__ __forceinline__ void sample_scale(
    int p, int k, float cx, float cy, int r, const __half* base, float* acc)
{
    const float rm1 = (float)(r - 1);
    float fx = (cx + 1.0f) * 0.5f * rm1;
    float fy = (cy + 1.0f) * 0.5f * rm1;
    fx = fminf(fmaxf(fx, 0.0f), rm1);
    fy = fminf(fmaxf(fy, 0.0f), rm1);

    const float x0f = floorf(fx);
    const float y0f = floorf(fy);
    const float wx = fx - x0f;
    const float wy = fy - y0f;
    const int x0 = (int)x0f;
    const int y0 = (int)y0f;
    const int x1 = min(x0 + 1, r - 1);
    const int y1 = min(y0 + 1, r - 1);

    const size_t row0 = (size_t)(p * r + y0) * r;
    const size_t row1 = (size_t)(p * r + y1) * r;

    const uint4 u00 = __ldg((const uint4*)(base + (row0 + x0) * CDIM) + k);
    const uint4 u01 = __ldg((const uint4*)(base + (row0 + x1) * CDIM) + k);
    const uint4 u10 = __ldg((const uint4*)(base + (row1 + x0) * CDIM) + k);
    const uint4 u11 = __ldg((const uint4*)(base + (row1 + x1) * CDIM) + k);

    const float w00 = (1.0f - wx) * (1.0f - wy);
    const float w01 = wx * (1.0f - wy);
    const float w10 = (1.0f - wx) * wy;
    const float w11 = wx * wy;

    #pragma unroll
    for (int h = 0; h < 4; h++) {
        const unsigned a00 = (&u00.x)[h], a01 = (&u01.x)[h];
        const unsigned a10 = (&u10.x)[h], a11 = (&u11.x)[h];
        float2 f00 = __half22float2(*(const __half2*)&a00);
        float2 f01 = __half22float2(*(const __half2*)&a01);
        float2 f10 = __half22float2(*(const __half2*)&a10);
        float2 f11 = __half22float2(*(const __half2*)&a11);
        acc[2*h+0] += f00.x * w00 + f01.x * w01 + f10.x * w10 + f11.x * w11;
        acc[2*h+1] += f00.y * w00 + f01.y * w01 + f10.y * w10 + f11.y * w11;
    }
}

// ---------------- gather scales 0-2 (small grids, L2-resident) ----------------
__global__ __launch_bounds__(256) void gather012_k(
    float* __restrict__ out, int N)
{
    const int gid = blockIdx.x * blockDim.x + threadIdx.x;
    if (gid >= N * THREADS_PER_PT) return;

    const int n = gid / THREADS_PER_PT;
    const int j = gid - n * THREADS_PER_PT;
    const int p = j / NCHUNK_H;
    const int k = j - p * NCHUNK_H;

    const float d0 = -0.625f * g_ptss[3 * n + 0];
    const float d1 = -0.625f * g_ptss[3 * n + 1];
    const float d2 = -0.625f * g_ptss[3 * n + 2];
    const float cx = (p == 2) ? d1 : d0;
    const float cy = (p == 0) ? d1 : d2;

    const int resos[3] = {64, 128, 256};
    const int offs[3]  = {0, 884736, 4423680};

    const int orig = g_perm[n];
    float* outrow = out + (size_t)orig * 864 + p * CDIM + k * 8;

    float acc[8];
    #pragma unroll
    for (int i = 0; i < 8; i++) acc[i] = 0.0f;

    #pragma unroll
    for (int s = 0; s < 3; s++) {
        sample_scale(p, k, cx, cy, resos[s], g_tph + offs[s], acc);
        float4 lo = make_float4(acc[0], acc[1], acc[2], acc[3]);
        float4 hi = make_float4(acc[4], acc[5], acc[6], acc[7]);
        float4* dst = (float4*)(outrow + s * 216);
        if (s < 2) {            // streaming: not re-read
            __stcs(dst, lo);
            __stcs(dst + 1, hi);
        } else {                // block 2: keep in L2, gather3 reads it back
            dst[0] = lo;
            dst[1] = hi;
        }
    }
}

// ---------------- gather scale 3 (block2 readback + s3 corners) ----------------
__global__ __launch_bounds__(256) void gather3_k(
    float* __restrict__ out, int N)
{
    const int gid = blockIdx.x * blockDim.x + threadIdx.x;
    if (gid >= N * THREADS_PER_PT) return;

    const int n = gid / THREADS_PER_PT;
    const int j = gid - n * THREADS_PER_PT;
    const int p = j / NCHUNK_H;
    const int k = j - p * NCHUNK_H;

    const float d0 = -0.625f * g_ptss[3 * n + 0];
    const float d1 = -0.625f * g_ptss[3 * n + 1];
    const float d2 = -0.625f * g_ptss[3 * n + 2];
    const float cx = (p == 2) ? d1 : d0;
    const float cy = (p == 0) ? d1 : d2;

    const int orig = g_perm[n];
    float* outrow = out + (size_t)orig * 864 + p * CDIM + k * 8;

    // cumulative value after scale 2 = output block 2
    const float4 lo2 = *((const float4*)(outrow + 2 * 216));
    const float4 hi2 = *((const float4*)(outrow + 2 * 216) + 1);
    float acc[8] = {lo2.x, lo2.y, lo2.z, lo2.w, hi2.x, hi2.y, hi2.z, hi2.w};

    sample_scale(p, k, cx, cy, 512, g_tph + 18579456, acc);

    __stcs((float4*)(outrow + 3 * 216),
           make_float4(acc[0], acc[1], acc[2], acc[3]));
    __stcs((float4*)(outrow + 3 * 216) + 1,
           make_float4(acc[4], acc[5], acc[6], acc[7]));
}

extern "C" void kernel_launch(void* const* d_in, const int* in_sizes, int n_in,
                              void* d_out, int out_size)
{
    const float* pts = (const float*)d_in[0];
    const int N = in_sizes[0] / 3;
    float* out = (float*)d_out;

    static const int res[4]  = {64, 128, 256, 512};
    static const int offs[4] = {0, 884736, 4423680, 18579456};

    static cudaStream_t s_side = nullptr;
    static cudaEvent_t  s_ev_fork = nullptr, s_ev_join = nullptr;
    static bool s_init = false;
    if (!s_init) {
        s_init = true;
        if (cudaStreamCreateWithFlags(&s_side, cudaStreamNonBlocking) != cudaSuccess)
            s_side = nullptr;
        cudaEventCreateWithFlags(&s_ev_fork, cudaEventDisableTiming);
        cudaEventCreateWithFlags(&s_ev_join, cudaEventDisableTiming);
    }
    const bool fork = (s_side != nullptr && s_ev_fork && s_ev_join);
    cudaStream_t sb = fork ? s_side : (cudaStream_t)0;

    if (fork) {
        cudaEventRecord(s_ev_fork, 0);
        cudaStreamWaitEvent(sb, s_ev_fork, 0);
    }

    // Stream A: the big scale-3 transpose (critical path)
    {
        const float* g = (const float*)d_in[4];
        const int r2 = 512 * 512;
        dim3 grid(r2 / 64, 3);
        transpose_k<<<grid, 288>>>(g, offs[3], r2);
    }

    // Stream B: sort + small transposes + gather of scales 0-2
    hist_k<<<(N + 255) / 256, 256, 0, sb>>>(pts, N);
    scan_k<<<1, 512, 0, sb>>>();
    scatter_k<<<(N + 255) / 256, 256, 0, sb>>>(pts, N);
    for (int s = 0; s < 3; s++) {
        const float* g = (const float*)d_in[1 + s];
        const int r2 = res[s] * res[s];
        dim3 grid(r2 / 64, 3);
        transpose_k<<<grid, 288, 0, sb>>>(g, offs[s], r2);
    }
    const int total = N * THREADS_PER_PT;
    gather012_k<<<(total + 255) / 256, 256, 0, sb>>>(out, N);

    if (fork) {
        cudaEventRecord(s_ev_join, sb);
        cudaStreamWaitEvent(0, s_ev_join, 0);
    }

    // gather3: needs s3 transpose (stream A) + block2 writes (stream B)
    gather3_k<<<(total + 255) / 256, 256>>>(out, N);
}

// round 11
// speedup vs baseline: 1.1939x; 1.1939x over previous
#include <cuda_runtime.h>
#include <cuda_fp16.h>

// Triplane sampling, GB300 (sm_103a).
// capture stream: transpose s0,s1,s2 -> gather (internally: sample s0-2,
//                 write out blocks 0-2, flag-wait for s3 transpose, sample s3)
//                 -> waitEvent(join)
// side stream:    transpose s3 (fp32->fp16, 339MB), each block bumps g_done
// No point sort: fp16 s3 table (113MB) ~fits L2, so corner reuse survives any
// point order; original order makes output writes perfectly sequential.

#define CDIM 72
#define NCHUNK_H 9           // 72 / 8 halves per uint4 chunk
#define THREADS_PER_PT 27    // 3 planes * 9 chunks
#define S3_BLOCKS (4096 * 3) // transpose_k grid for r=512

__device__ __half g_tph[75202560];   // 150.4 MB fp16 scratch, channel-major
__device__ int    g_done = 0;        // s3 transpose blocks completed
__device__ int    g_fin  = 0;        // gather blocks completed (for reset)

__device__ __forceinline__ unsigned h2_bits(__half2 h) {
    union { __half2 h; unsigned u; } cv;
    cv.h = h;
    return cv.u;
}

// ---------------- transpose: [3,72,r2] fp32 -> [3, r2, 72] fp16 ----------------
__global__ __launch_bounds__(288) void transpose_k(
    const float* __restrict__ in, int off, int r2, int notify)
{
    __shared__ float tile[64 * 77];
    const int p   = blockIdx.y;
    const int t0  = blockIdx.x * 64;
    const int tid = threadIdx.x;

    const float* src = in + (size_t)p * CDIM * r2 + t0;
    #pragma unroll
    for (int i = 0; i < 4; i++) {
        int idx = i * 288 + tid;          // 0..1151
        int c = idx >> 4;                 // channel 0..71
        int v = idx & 15;                 // float4 index over 64 texels
        float4 d = __ldg((const float4*)(src + (size_t)c * r2) + v);
        float* tp = tile + (4 * v) * 77 + c;
        tp[0 * 77] = d.x;
        tp[1 * 77] = d.y;
        tp[2 * 77] = d.z;
        tp[3 * 77] = d.w;
    }
    __syncthreads();

    uint4* dst = (uint4*)(g_tph + off) + ((size_t)p * r2 + t0) * NCHUNK_H;
    #pragma unroll
    for (int i = 0; i < 2; i++) {
        int lin = i * 288 + tid;          // 0..575
        int x = lin / NCHUNK_H;
        int q = lin - x * NCHUNK_H;
        const float* tp = tile + x * 77 + 8 * q;
        uint4 o;
        o.x = h2_bits(__floats2half2_rn(tp[0], tp[1]));
        o.y = h2_bits(__floats2half2_rn(tp[2], tp[3]));
        o.z = h2_bits(__floats2half2_rn(tp[4], tp[5]));
        o.w = h2_bits(__floats2half2_rn(tp[6], tp[7]));
        dst[lin] = o;
    }

    if (notify) {
        __syncthreads();
        if (tid == 0) {
            __threadfence();
            atomicAdd(&g_done, 1);
        }
    }
}

// ---------------- bilinear corner fetch for one scale ----------------
__device__ __forceinline__ void sample_scale(
    int p, int k, float cx, float cy, int r, const __half* __restrict__ base,
    float* acc)
{
    const float rm1 = (float)(r - 1);
    float fx = (cx + 1.0f) * 0.5f * rm1;
    float fy = (cy + 1.0f) * 0.5f * rm1;
    fx = fminf(fmaxf(fx, 0.0f), rm1);
    fy = fminf(fmaxf(fy, 0.0f), rm1);

    const float x0f = floorf(fx);
    const float y0f = floorf(fy);
    const float wx = fx - x0f;
    const float wy = fy - y0f;
    const int x0 = (int)x0f;
    const int y0 = (int)y0f;
    const int x1 = min(x0 + 1, r - 1);
    const int y1 = min(y0 + 1, r - 1);

    const unsigned row0 = (unsigned)(p * r + y0) * (unsigned)r;
    const unsigned row1 = (unsigned)(p * r + y1) * (unsigned)r;

    const uint4 u00 = __ldg((const uint4*)(base + (size_t)(row0 + x0) * CDIM) + k);
    const uint4 u01 = __ldg((const uint4*)(base + (size_t)(row0 + x1) * CDIM) + k);
    const uint4 u10 = __ldg((const uint4*)(base + (size_t)(row1 + x0) * CDIM) + k);
    const uint4 u11 = __ldg((const uint4*)(base + (size_t)(row1 + x1) * CDIM) + k);

    const float w00 = (1.0f - wx) * (1.0f - wy);
    const float w01 = wx * (1.0f - wy);
    const float w10 = (1.0f - wx) * wy;
    const float w11 = wx * wy;

    #pragma unroll
    for (int h = 0; h < 4; h++) {
        const unsigned a00 = (&u00.x)[h], a01 = (&u01.x)[h];
        const unsigned a10 = (&u10.x)[h], a11 = (&u11.x)[h];
        float2 f00 = __half22float2(*(const __half2*)&a00);
        float2 f01 = __half22float2(*(const __half2*)&a01);
        float2 f10 = __half22float2(*(const __half2*)&a10);
        float2 f11 = __half22float2(*(const __half2*)&a11);
        acc[2*h+0] += f00.x * w00 + f01.x * w01 + f10.x * w10 + f11.x * w11;
        acc[2*h+1] += f00.y * w00 + f01.y * w01 + f10.y * w10 + f11.y * w11;
    }
}

// ---------------- gather (original point order; flag-fused with s3 transpose) --
__global__ __launch_bounds__(256) void gather_k(
    const float* __restrict__ pts, float* __restrict__ out, int N)
{
    const int gid = blockIdx.x * blockDim.x + threadIdx.x;
    const int total = N * THREADS_PER_PT;
    const bool valid = (gid < total);

    int p = 0, k = 0;
    float cx = 0.f, cy = 0.f;
    float* outrow = out;
    float acc[8];
    #pragma unroll
    for (int i = 0; i < 8; i++) acc[i] = 0.0f;

    if (valid) {
        const int n = gid / THREADS_PER_PT;
        const int j = gid - n * THREADS_PER_PT;
        p = j / NCHUNK_H;
        k = j - p * NCHUNK_H;

        const float d0 = -0.625f * __ldg(&pts[3 * n + 0]);
        const float d1 = -0.625f * __ldg(&pts[3 * n + 1]);
        const float d2 = -0.625f * __ldg(&pts[3 * n + 2]);
        cx = (p == 2) ? d1 : d0;
        cy = (p == 0) ? d1 : d2;

        outrow = out + (size_t)n * 864 + p * CDIM + k * 8;

        // scales 0-2 (need only the small transposes, already done on this stream)
        const int resos[3] = {64, 128, 256};
        const int offs[3]  = {0, 884736, 4423680};
        #pragma unroll
        for (int s = 0; s < 3; s++) {
            sample_scale(p, k, cx, cy, resos[s], g_tph + offs[s], acc);
            __stcs((float4*)(outrow + s * 216),
                   make_float4(acc[0], acc[1], acc[2], acc[3]));
            __stcs((float4*)(outrow + s * 216) + 1,
                   make_float4(acc[4], acc[5], acc[6], acc[7]));
        }
    }

    // wait for the s3 transpose (runs concurrently on the side stream)
    if (threadIdx.x == 0) {
        while (atomicAdd(&g_done, 0) < S3_BLOCKS) __nanosleep(128);
        __threadfence();
    }
    __syncthreads();

    if (valid) {
        sample_scale(p, k, cx, cy, 512, g_tph + 18579456, acc);
        __stcs((float4*)(outrow + 3 * 216),
               make_float4(acc[0], acc[1], acc[2], acc[3]));
        __stcs((float4*)(outrow + 3 * 216) + 1,
               make_float4(acc[4], acc[5], acc[6], acc[7]));
    }

    // replay-safe reset: last gather block zeroes the counters
    __syncthreads();
    if (threadIdx.x == 0) {
        int f = atomicAdd(&g_fin, 1);
        if (f == (int)gridDim.x - 1) {
            atomicExch(&g_done, 0);
            atomicExch(&g_fin, 0);
        }
    }
}

extern "C" void kernel_launch(void* const* d_in, const int* in_sizes, int n_in,
                              void* d_out, int out_size)
{
    const float* pts = (const float*)d_in[0];
    const int N = in_sizes[0] / 3;
    float* out = (float*)d_out;

    static const int res[4]  = {64, 128, 256, 512};
    static const int offs[4] = {0, 884736, 4423680, 18579456};

    static cudaStream_t s_side = nullptr;
    static cudaEvent_t  s_ev_fork = nullptr, s_ev_join = nullptr;
    static bool s_init = false;
    if (!s_init) {
        s_init = true;
        if (cudaStreamCreateWithFlags(&s_side, cudaStreamNonBlocking) != cudaSuccess)
            s_side = nullptr;
        cudaEventCreateWithFlags(&s_ev_fork, cudaEventDisableTiming);
        cudaEventCreateWithFlags(&s_ev_join, cudaEventDisableTiming);
    }
    const bool fork = (s_side != nullptr && s_ev_fork && s_ev_join);
    cudaStream_t sb = fork ? s_side : (cudaStream_t)0;

    if (fork) {
        cudaEventRecord(s_ev_fork, 0);
        cudaStreamWaitEvent(sb, s_ev_fork, 0);
    }

    // Side stream: the big s3 transpose; blocks bump g_done as they finish.
    {
        const float* g = (const float*)d_in[4];
        const int r2 = 512 * 512;
        dim3 grid(r2 / 64, 3);
        transpose_k<<<grid, 288, 0, sb>>>(g, offs[3], r2, 1);
    }

    // Capture stream: small transposes, then gather (flag-waits for s3 inside).
    for (int s = 0; s < 3; s++) {
        const float* g = (const float*)d_in[1 + s];
        const int r2 = res[s] * res[s];
        dim3 grid(r2 / 64, 3);
        transpose_k<<<grid, 288>>>(g, offs[s], r2, 0);
    }
    const int total = N * THREADS_PER_PT;
    gather_k<<<(total + 255) / 256, 256>>>(pts, out, N);

    // Join the side stream after gather (required for valid capture; adds no
    // critical-path dependency since gather already waited via the flag).
    if (fork) {
        cudaEventRecord(s_ev_join, sb);
        cudaStreamWaitEvent(0, s_ev_join, 0);
    }
}